// round 1
// baseline (speedup 1.0000x reference)
#include <cuda_runtime.h>
#include <cstdint>

// Farthest Point Sampling on GB300.
// One cluster of 8 CTAs per batch (8 batches -> 64 CTAs / 64 SMs).
// Coords SMEM-resident (SoA, 16384 pts/CTA = 192KB), min-dist register-resident
// (8x float2 per thread). Per step: packed-f32x2 distance update + min + local
// argmax, warp shfl reduce, CTA smem reduce, cluster DSMEM all-gather of the
// per-CTA candidate {v, gidx, x, y, z}, one barrier.cluster per step
// (double-buffered candidate slots by parity).

#define NPTS     131072
#define BATCH    8
#define NSAMP    4096
#define CSIZE    8
#define PPC      (NPTS / CSIZE)        // 16384 points per CTA
#define NTHREADS 1024
#define NPAIRS   (PPC / 2)             // 8192
#define PAIRS_PT (NPAIRS / NTHREADS)   // 8
#define BIGF     1e10f

#define SMEM_FLOATS (3 * PPC + 64 + 2 * CSIZE * 8)
#define SMEM_BYTES  (SMEM_FLOATS * sizeof(float))

// Packed fp32x2 ops (Blackwell). add/mul .rn are bit-identical to scalar rn ops,
// so results match the reference's mul-then-add elementwise arithmetic exactly.
#define ADD2(o, a, b) asm("add.rn.f32x2 %0, %1, %2;" : "=l"(o) : "l"(a), "l"(b))
#define MUL2(o, a, b) asm("mul.rn.f32x2 %0, %1, %2;" : "=l"(o) : "l"(a), "l"(b))
#define PACK2(o, lo, hi) asm("mov.b64 %0, {%1, %2};" : "=l"(o) : "f"(lo), "f"(hi))
#define UNPACK2(lo, hi, in) asm("mov.b64 {%0, %1}, %2;" : "=f"(lo), "=f"(hi) : "l"(in))

static __device__ __forceinline__ uint32_t smem_u32(const void* p) {
    uint32_t a;
    asm("{ .reg .u64 t; cvta.to.shared.u64 t, %1; cvt.u32.u64 %0, t; }"
        : "=r"(a) : "l"(p));
    return a;
}
static __device__ __forceinline__ uint32_t mapa_rank(uint32_t local, uint32_t rank) {
    uint32_t r;
    asm("mapa.shared::cluster.u32 %0, %1, %2;" : "=r"(r) : "r"(local), "r"(rank));
    return r;
}
static __device__ __forceinline__ void st_cluster_b32(uint32_t addr, uint32_t v) {
    asm volatile("st.shared::cluster.b32 [%0], %1;" :: "r"(addr), "r"(v) : "memory");
}

__global__ void __cluster_dims__(CSIZE, 1, 1) __launch_bounds__(NTHREADS, 1)
fps_kernel(const float* __restrict__ pts, float* __restrict__ out)
{
    extern __shared__ float sm[];
    float* smx  = sm;                  // x coords, [PPC]
    float* smy  = sm + PPC;            // y coords
    float* smz  = sm + 2 * PPC;        // z coords
    float* wv   = sm + 3 * PPC;        // per-warp best value, [32]
    int*   wi   = (int*)(wv + 32);     // per-warp best index, [32]
    float* cand = wv + 64;             // [2][CSIZE][8] candidate slots (parity-buffered)

    const int tid = threadIdx.x;
    uint32_t rank;
    asm("mov.u32 %0, %%cluster_ctarank;" : "=r"(rank));
    const int b = blockIdx.x / CSIZE;
    const float* P = pts + (size_t)b * NPTS * 3;
    const int base = (int)rank * PPC;

    // Load this CTA's 16384 points into SMEM (SoA).
    for (int i = tid; i < PPC; i += NTHREADS) {
        const float* g = P + (size_t)(base + i) * 3;
        smx[i] = g[0];
        smy[i] = g[1];
        smz[i] = g[2];
    }

    // Register-resident running min distance: 8 pairs per thread.
    float2 md[PAIRS_PT];
#pragma unroll
    for (int j = 0; j < PAIRS_PT; j++) md[j] = make_float2(BIGF, BIGF);

    __syncthreads();

    // Initial "last" point = point 0 of the batch (reference: last_idx init 0).
    float lx = P[0], ly = P[1], lz = P[2];
    int parity = 0;
    const uint32_t cand_u32 = smem_u32(cand);

    for (int s = 0; s < NSAMP; s++) {
        // Reference scan emits last_idx BEFORE the update, so output coords of
        // the current last point first.
        if (rank == 0 && tid == 0) {
            float* o = out + ((size_t)b * NSAMP + s) * 3;
            o[0] = lx; o[1] = ly; o[2] = lz;
        }

        unsigned long long NX, NY, NZ;
        {
            float nx = -lx, ny = -ly, nz = -lz;  // x + (-l) == x - l bit-exact (rn)
            PACK2(NX, nx, nx);
            PACK2(NY, ny, ny);
            PACK2(NZ, nz, nz);
        }

        float bestv = -1.0f;
        int   besti = 0;
#pragma unroll
        for (int j = 0; j < PAIRS_PT; j++) {
            const int q = j * NTHREADS + tid;   // pair index; points 2q, 2q+1
            unsigned long long X = ((const unsigned long long*)smx)[q];
            unsigned long long Y = ((const unsigned long long*)smy)[q];
            unsigned long long Z = ((const unsigned long long*)smz)[q];
            unsigned long long dx, dy, dz, s2;
            ADD2(dx, X, NX);
            ADD2(dy, Y, NY);
            ADD2(dz, Z, NZ);
            MUL2(dx, dx, dx);
            MUL2(dy, dy, dy);
            MUL2(dz, dz, dz);
            ADD2(s2, dx, dy);      // (dx^2 + dy^2)
            ADD2(s2, s2, dz);      // + dz^2  — same order as jnp.sum over axis -1
            float d0, d1;
            UNPACK2(d0, d1, s2);
            float m0 = fminf(md[j].x, d0);
            float m1 = fminf(md[j].y, d1);
            md[j].x = m0;
            md[j].y = m1;
            // Strict '>' => first (lowest) index wins on exact ties, matching
            // jnp.argmax (within-thread indices are increasing in j, .x then .y).
            if (m0 > bestv) { bestv = m0; besti = 2 * q; }
            if (m1 > bestv) { bestv = m1; besti = 2 * q + 1; }
        }

        // Warp butterfly reduce: max value, tie -> min index.
#pragma unroll
        for (int off = 16; off; off >>= 1) {
            float ov = __shfl_xor_sync(0xffffffffu, bestv, off);
            int   oi = __shfl_xor_sync(0xffffffffu, besti, off);
            if (ov > bestv || (ov == bestv && oi < besti)) { bestv = ov; besti = oi; }
        }
        const int warp = tid >> 5;
        if ((tid & 31) == 0) { wv[warp] = bestv; wi[warp] = besti; }
        __syncthreads();

        if (warp == 0) {
            bestv = wv[tid];
            besti = wi[tid];
#pragma unroll
            for (int off = 16; off; off >>= 1) {
                float ov = __shfl_xor_sync(0xffffffffu, bestv, off);
                int   oi = __shfl_xor_sync(0xffffffffu, besti, off);
                if (ov > bestv || (ov == bestv && oi < besti)) { bestv = ov; besti = oi; }
            }
            // All 32 lanes now hold the CTA winner. Lanes 0..7 broadcast the
            // candidate {v, gidx, x, y, z} into slot [parity][myrank] of every
            // cluster CTA via DSMEM.
            if (tid < CSIZE) {
                float cx = smx[besti], cy = smy[besti], cz = smz[besti];
                uint32_t dst = mapa_rank(
                    cand_u32 + (uint32_t)(parity * CSIZE + (int)rank) * 32u,
                    (uint32_t)tid);
                st_cluster_b32(dst +  0, __float_as_uint(bestv));
                st_cluster_b32(dst +  4, (uint32_t)(base + besti));
                st_cluster_b32(dst +  8, __float_as_uint(cx));
                st_cluster_b32(dst + 12, __float_as_uint(cy));
                st_cluster_b32(dst + 16, __float_as_uint(cz));
            }
        }

        // One cluster barrier per step; candidate slots double-buffered by
        // parity so this single sync both publishes this step's writes and
        // protects last step's buffer.
        asm volatile("barrier.cluster.arrive.aligned;" ::: "memory");
        asm volatile("barrier.cluster.wait.aligned;" ::: "memory");

        // Every thread reduces the 8 candidates identically (broadcast LDS).
        float bv = -1.0f;
        int   bi = 0x7fffffff;
        float bx = 0.f, by = 0.f, bz = 0.f;
#pragma unroll
        for (int r = 0; r < CSIZE; r++) {
            const float* c = cand + (parity * CSIZE + r) * 8;
            float v = c[0];
            int  gi = ((const int*)c)[1];
            if (v > bv || (v == bv && gi < bi)) {
                bv = v; bi = gi; bx = c[2]; by = c[3]; bz = c[4];
            }
        }
        lx = bx; ly = by; lz = bz;
        parity ^= 1;
    }
}

extern "C" void kernel_launch(void* const* d_in, const int* in_sizes, int n_in,
                              void* d_out, int out_size)
{
    (void)in_sizes; (void)n_in; (void)out_size;
    const float* pts = (const float*)d_in[0];   // point_coord (8, 131072, 3)
    float* out = (float*)d_out;                 // (8, 4096, 3)

    cudaFuncSetAttribute(fps_kernel,
                         cudaFuncAttributeMaxDynamicSharedMemorySize,
                         (int)SMEM_BYTES);

    fps_kernel<<<BATCH * CSIZE, NTHREADS, SMEM_BYTES>>>(pts, out);
}